// round 1
// baseline (speedup 1.0000x reference)
#include <cuda_runtime.h>
#include <cstdint>

// EdgeEmbedding: out[i, :] = edge_type_embedding[data[i], :] + type_attr_sum[data[i], :]
// where type_attr_sum[t] = sum over attrs assigned to type t of attr_table[attr_id].
//
// Strategy:
//   comb[t, :] = edge_type_embedding[t, :] + segment_sum(attr_table[flat_attr_ids], attr_seg_ids)[t, :]
//   out[i, :]  = comb[data[i], :]
// comb is only 1000 x 256 f32 = 1 MB -> lives in a __device__ global, stays L2-resident
// for the main gather, which is then pure write-bandwidth bound.

#define NUM_TYPES 1000
#define DIM 256
#define DIM4 (DIM / 4)   // 64 float4 per row

__device__ float g_comb[NUM_TYPES * DIM];

// ---------------------------------------------------------------------------
// Phase 1: comb[t, d] = edge_type_embedding[t, d]
// ---------------------------------------------------------------------------
__global__ void init_comb_kernel(const float* __restrict__ ete) {
    int idx = blockIdx.x * blockDim.x + threadIdx.x;
    if (idx < NUM_TYPES * DIM4) {
        const float4* src = reinterpret_cast<const float4*>(ete);
        float4* dst = reinterpret_cast<float4*>(g_comb);
        dst[idx] = src[idx];
    }
}

// ---------------------------------------------------------------------------
// Phase 2: comb[seg[a], d] += attr_table[id[a], d]   (atomic segment sum)
// One thread per (attr, 4-float chunk): reads a float4, does 4 atomicAdds.
// ---------------------------------------------------------------------------
__global__ void segsum_kernel(const float* __restrict__ attr_table,
                              const int* __restrict__ flat_attr_ids,
                              const int* __restrict__ attr_seg_ids,
                              int total_attrs) {
    int gid = blockIdx.x * blockDim.x + threadIdx.x;
    int total = total_attrs * DIM4;
    if (gid >= total) return;
    int a = gid >> 6;           // attr index (gid / 64)
    int c = gid & (DIM4 - 1);   // float4 chunk within row
    int id  = flat_attr_ids[a];
    int seg = attr_seg_ids[a];
    float4 v = reinterpret_cast<const float4*>(attr_table)[(long long)id * DIM4 + c];
    float* dst = &g_comb[seg * DIM + c * 4];
    atomicAdd(dst + 0, v.x);
    atomicAdd(dst + 1, v.y);
    atomicAdd(dst + 2, v.z);
    atomicAdd(dst + 3, v.w);
}

// ---------------------------------------------------------------------------
// Phase 3: out[i, :] = comb[data[i], :]
// 64 threads (float4 lanes) per edge; comb row read hits L2 (1 MB table),
// output stores are fully coalesced 128-bit.
// ---------------------------------------------------------------------------
__global__ void gather_kernel(const int* __restrict__ data,
                              float4* __restrict__ out,
                              int n) {
    long long gid = (long long)blockIdx.x * blockDim.x + threadIdx.x;
    long long total = (long long)n * DIM4;
    if (gid >= total) return;
    int i = (int)(gid >> 6);        // edge index
    int c = (int)(gid & (DIM4 - 1));
    int t = __ldg(&data[i]);        // broadcast across the 64 lanes of this edge
    float4 v = reinterpret_cast<const float4*>(g_comb)[t * DIM4 + c];
    out[gid] = v;
}

// ---------------------------------------------------------------------------
// Launch. Inputs (metadata order):
//   d_in[0] data              [N]           int32
//   d_in[1] attr_table        [200000*256]  float32
//   d_in[2] edge_type_embed   [1000*256]    float32
//   d_in[3] flat_attr_ids     [50000]       int32
//   d_in[4] attr_seg_ids      [50000]       int32
// out: [N*256] float32
// ---------------------------------------------------------------------------
extern "C" void kernel_launch(void* const* d_in, const int* in_sizes, int n_in,
                              void* d_out, int out_size) {
    const int*   data        = (const int*)d_in[0];
    const float* attr_table  = (const float*)d_in[1];
    const float* ete         = (const float*)d_in[2];
    const int*   flat_ids    = (const int*)d_in[3];
    const int*   seg_ids     = (const int*)d_in[4];
    float4*      out         = (float4*)d_out;

    int n           = in_sizes[0];
    int total_attrs = in_sizes[3];

    // Phase 1: init comb with edge-type embedding
    {
        int work = NUM_TYPES * DIM4;
        init_comb_kernel<<<(work + 255) / 256, 256>>>(ete);
    }
    // Phase 2: atomic segment sum of attr embeddings into comb
    {
        int work = total_attrs * DIM4;
        segsum_kernel<<<(work + 255) / 256, 256>>>(attr_table, flat_ids, seg_ids,
                                                   total_attrs);
    }
    // Phase 3: main gather (bandwidth-bound)
    {
        long long work = (long long)n * DIM4;
        int block = 256;
        long long grid = (work + block - 1) / block;
        gather_kernel<<<(unsigned)grid, block>>>(data, out, n);
    }
}

// round 3
// speedup vs baseline: 1.2403x; 1.2403x over previous
#include <cuda_runtime.h>
#include <cstdint>

// EdgeEmbedding: out[i, :] = edge_type_embedding[data[i], :] + type_attr_sum[data[i], :]
//
//   comb[t, :] = ete[t, :] + segment_sum(attr_table[flat_attr_ids], attr_seg_ids)[t, :]
//   out[i, :]  = comb[data[i], :]
//
// R1 change (unbenched in R2 due to broker timeout; resubmitting): the main
// gather no longer reads comb through L2 (was ~1 GB of LTS read traffic on top
// of the 1 GB write). Instead the 1 MB comb table is partitioned into 5 slices
// of 200 types (200 KB each); each CTA holds one slice in shared memory and
// scans a chunk of the edge list, writing rows for edges whose type falls
// inside its slice. Each edge is written exactly once.

#define NUM_TYPES 1000
#define DIM 256
#define DIM4 (DIM / 4)          // 64 float4 per row

#define TYPES_PER_SLICE 200
#define NUM_SLICES 5            // 5 * 200 = 1000
#define BLOCKS_PER_SLICE 29     // 5 * 29 = 145 CTAs ~ one per SM
#define GATHER_THREADS 512
#define SLICE_SMEM_BYTES (TYPES_PER_SLICE * DIM * sizeof(float))  // 204800

__device__ float g_comb[NUM_TYPES * DIM];

// ---------------------------------------------------------------------------
// Phase 1: comb[t, d] = edge_type_embedding[t, d]
// ---------------------------------------------------------------------------
__global__ void init_comb_kernel(const float* __restrict__ ete) {
    int idx = blockIdx.x * blockDim.x + threadIdx.x;
    if (idx < NUM_TYPES * DIM4) {
        const float4* src = reinterpret_cast<const float4*>(ete);
        float4* dst = reinterpret_cast<float4*>(g_comb);
        dst[idx] = src[idx];
    }
}

// ---------------------------------------------------------------------------
// Phase 2: comb[seg[a], d] += attr_table[id[a], d]   (atomic segment sum)
// ---------------------------------------------------------------------------
__global__ void segsum_kernel(const float* __restrict__ attr_table,
                              const int* __restrict__ flat_attr_ids,
                              const int* __restrict__ attr_seg_ids,
                              int total_attrs) {
    int gid = blockIdx.x * blockDim.x + threadIdx.x;
    int total = total_attrs * DIM4;
    if (gid >= total) return;
    int a = gid >> 6;           // attr index
    int c = gid & (DIM4 - 1);   // float4 chunk within row
    int id  = flat_attr_ids[a];
    int seg = attr_seg_ids[a];
    float4 v = reinterpret_cast<const float4*>(attr_table)[(long long)id * DIM4 + c];
    float* dst = &g_comb[seg * DIM + c * 4];
    atomicAdd(dst + 0, v.x);
    atomicAdd(dst + 1, v.y);
    atomicAdd(dst + 2, v.z);
    atomicAdd(dst + 3, v.w);
}

// ---------------------------------------------------------------------------
// Phase 3: smem-sliced gather.
// CTA (slice, b): load comb[slice*200 .. +200) into smem, scan edge chunk b,
// and for every edge whose type is in-slice, the warp copies the 1 KB row
// smem -> out. Writes are 1 KB contiguous per edge (2x STG.128 per lane).
// ---------------------------------------------------------------------------
__global__ void __launch_bounds__(GATHER_THREADS, 1)
gather_smem_kernel(const int* __restrict__ data,
                   float4* __restrict__ out,
                   int n) {
    extern __shared__ float4 s_comb[];   // TYPES_PER_SLICE * 64 float4

    int slice = blockIdx.x / BLOCKS_PER_SLICE;
    int b     = blockIdx.x % BLOCKS_PER_SLICE;
    int t_lo  = slice * TYPES_PER_SLICE;
    int t_hi  = t_lo + TYPES_PER_SLICE;
    if (t_hi > NUM_TYPES) t_hi = NUM_TYPES;
    int nt = t_hi - t_lo;

    // Load this slice of comb into shared memory (fully coalesced float4).
    const float4* comb4 = reinterpret_cast<const float4*>(g_comb);
    for (int i = threadIdx.x; i < nt * DIM4; i += GATHER_THREADS)
        s_comb[i] = comb4[t_lo * DIM4 + i];
    __syncthreads();

    // Edge chunk for this b (same chunk is scanned by all 5 slices; union of
    // slices covers every type, so each edge is written exactly once).
    int chunk = (n + BLOCKS_PER_SLICE - 1) / BLOCKS_PER_SLICE;
    int e0 = b * chunk;
    int e1 = e0 + chunk;
    if (e1 > n) e1 = n;

    int warp = threadIdx.x >> 5;
    int lane = threadIdx.x & 31;
    const int NW = GATHER_THREADS / 32;

    for (int base = e0 + warp * 32; base < e1; base += NW * 32) {
        int e = base + lane;
        int t = -1;
        if (e < e1) t = __ldg(&data[e]);
        bool match = (t >= t_lo) && (t < t_hi);
        unsigned m = __ballot_sync(0xffffffffu, match);
        while (m) {
            int j = __ffs(m) - 1;
            m &= m - 1;
            int tj = __shfl_sync(0xffffffffu, t, j);
            long long ej = (long long)base + j;
            const float4* src = &s_comb[(tj - t_lo) * DIM4];
            float4* dst = out + ej * DIM4;
            dst[lane]      = src[lane];
            dst[lane + 32] = src[lane + 32];
        }
    }
}

// ---------------------------------------------------------------------------
// Launch. Inputs (metadata order):
//   d_in[0] data              [N]           int32
//   d_in[1] attr_table        [200000*256]  float32
//   d_in[2] edge_type_embed   [1000*256]    float32
//   d_in[3] flat_attr_ids     [50000]       int32
//   d_in[4] attr_seg_ids      [50000]       int32
// out: [N*256] float32
// ---------------------------------------------------------------------------
extern "C" void kernel_launch(void* const* d_in, const int* in_sizes, int n_in,
                              void* d_out, int out_size) {
    const int*   data        = (const int*)d_in[0];
    const float* attr_table  = (const float*)d_in[1];
    const float* ete         = (const float*)d_in[2];
    const int*   flat_ids    = (const int*)d_in[3];
    const int*   seg_ids     = (const int*)d_in[4];
    float4*      out         = (float4*)d_out;

    int n           = in_sizes[0];
    int total_attrs = in_sizes[3];

    // One-time-per-call attribute set (idempotent, host-side, pre-capture).
    static bool attr_set = false;
    if (!attr_set) {
        cudaFuncSetAttribute(gather_smem_kernel,
                             cudaFuncAttributeMaxDynamicSharedMemorySize,
                             SLICE_SMEM_BYTES);
        attr_set = true;
    }

    // Phase 1: init comb with edge-type embedding
    {
        int work = NUM_TYPES * DIM4;
        init_comb_kernel<<<(work + 255) / 256, 256>>>(ete);
    }
    // Phase 2: atomic segment sum of attr embeddings into comb
    {
        int work = total_attrs * DIM4;
        segsum_kernel<<<(work + 255) / 256, 256>>>(attr_table, flat_ids, seg_ids,
                                                   total_attrs);
    }
    // Phase 3: smem-sliced gather (HBM-write-bound)
    {
        gather_smem_kernel<<<NUM_SLICES * BLOCKS_PER_SLICE, GATHER_THREADS,
                             SLICE_SMEM_BYTES>>>(data, out, n);
    }
}